// round 6
// baseline (speedup 1.0000x reference)
#include <cuda_runtime.h>

#define L_SEQ 512
#define T_TAGS 64
#define CHAINS 8          // chains per CTA (2 warps each)
#define THREADS 512

#define FMA2(d, a, b) asm("fma.rn.f32x2 %0, %1, %2, %0;" : "+l"(d) : "l"(a), "l"(b))
#define ADD2(d, a)    asm("add.rn.f32x2 %0, %0, %1;"      : "+l"(d) : "l"(a))
#define BARC(id)      asm volatile("bar.sync %0, 64;" :: "r"(id) : "memory")

__device__ __forceinline__ unsigned long long pack2(float x, float y) {
    unsigned long long r;
    asm("mov.b64 %0, {%1, %2};" : "=l"(r) : "f"(x), "f"(y));
    return r;
}

__global__ __launch_bounds__(THREADS, 1)
void crf_kernel(const float* __restrict__ logits,
                const unsigned int* __restrict__ tagw,
                const int* __restrict__ mask,
                const float* __restrict__ trans,
                float* __restrict__ out)
{
    __shared__ float pbuf[2][CHAINS][68];   // p values, double-buffered, +pad
    __shared__ float sbuf[2][CHAINS];       // stale-shift slots, double-buffered
    __shared__ float red[CHAINS][2][4];     // epilogue scratch

    const int tid  = threadIdx.x;
    const int w    = tid >> 5;
    const int lane = tid & 31;
    const int c    = w >> 1;            // chain within CTA
    const int h    = w & 1;             // warp-half of the chain
    const int j    = (h << 5) + lane;   // this lane owns tag j (0..63)
    const int barid = 8 + c;            // named barrier per chain
    const int b    = blockIdx.x * CHAINS + c;

    // ---- tag dtype detection (int64 LE => odd 32-bit words all zero) ----
    unsigned oddacc = 0;
    #pragma unroll
    for (int k = 0; k < 4; ++k) oddacc |= tagw[2 * (lane + 32 * k) + 1];
    const int is64 = __all_sync(0xffffffffu, oddacc == 0) ? 1 : 0;

    // ---- register cache of exp(trans) column j, packed over i-pairs ----
    unsigned long long ec[32];
    #pragma unroll
    for (int i2 = 0; i2 < 32; ++i2) {
        float e0 = __expf(trans[(2 * i2) * 64 + j]);
        float e1 = __expf(trans[(2 * i2 + 1) * 64 + j]);
        ec[i2] = pack2(e0, e1);
    }

    const float* lg = logits + (size_t)b * (L_SEQ * T_TAGS);
    const int mbase = b * L_SEQ;

    // ---- l = 0 ----
    float al = lg[j];                           // one alpha per lane
    int t0 = (int)tagw[is64 ? (mbase << 1) : mbase];
    float gold = 0.f;
    {
        float m0 = (float)mask[mbase];
        if (t0 == j) gold = al * m0;
    }
    int tprev = t0;

    // prologue: publish alpha0[0] as shift for steps 1 and 2
    if (j == 0) { sbuf[0][c] = al; sbuf[1][c] = al; }
    BARC(barid);
    float shiftreg = sbuf[1][c];                // shift for step 1

    // current-step (l = 1) operands, prefetched
    float cem = lg[T_TAGS + j];
    int cm = mask[mbase + 1];
    int ct = (int)tagw[is64 ? ((mbase + 1) << 1) : (mbase + 1)];

    for (int l = 1; l < L_SEQ; ++l) {
        const int buf = l & 1;

        // depth-1 prefetch (clamped) + gold transition load
        const int lp = (l + 1 < L_SEQ) ? (l + 1) : (L_SEQ - 1);
        float nem = lg[lp * T_TAGS + j];
        int nm = mask[mbase + lp];
        int nt = (int)tagw[is64 ? ((mbase + lp) << 1) : (mbase + lp)];
        float tv = __ldg(&trans[tprev * 64 + ct]);

        // ---- p-phase: p = exp(alpha - shift), one value per lane ----
        float p = __expf(al - shiftreg);
        pbuf[buf][c][j] = p;
        BARC(barid);

        // prefetch shift for step l+1 (written at step l-1, visible after this bar)
        float nshift = sbuf[(l + 1) & 1][c];

        // ---- matvec: s[j] = sum_i p[i] * expT[i][j]; i packed in pairs ----
        const ulonglong2* pq = (const ulonglong2*)&pbuf[buf][c][0];  // 16 entries
        unsigned long long sA = 0ull, sB = 0ull, sC = 0ull, sD = 0ull;
        #pragma unroll
        for (int k = 0; k < 16; ++k) {
            ulonglong2 pp = pq[k];              // pairs (p[4k],p[4k+1]), (p[4k+2],p[4k+3])
            if (k & 1) {
                FMA2(sC, pp.x, ec[2 * k]);
                FMA2(sD, pp.y, ec[2 * k + 1]);
            } else {
                FMA2(sA, pp.x, ec[2 * k]);
                FMA2(sB, pp.y, ec[2 * k + 1]);
            }
        }
        ADD2(sA, sB);
        ADD2(sC, sD);
        ADD2(sA, sC);
        float slo, shi;
        asm("mov.b64 {%0, %1}, %2;" : "=f"(slo), "=f"(shi) : "l"(sA));
        float s = slo + shi;

        float n = shiftreg + __logf(s) + cem;
        bool keep = cm > 0;
        al = keep ? n : al;

        // publish shift for step l+2 (slot l&1)
        if (j == 0) sbuf[buf][c] = al;

        // ---- gold score ----
        float lm = (float)cm;
        if (ct == j) gold += cem * lm;
        if (j == 0) gold += tv * lm;
        tprev = ct;

        cem = nem; cm = nm; ct = nt; shiftreg = nshift;
    }

    // ---- epilogue: logsumexp over 64 alphas (32 per warp) + gold sum ----
    float mx = al;
    #pragma unroll
    for (int d = 1; d < 32; d <<= 1)
        mx = fmaxf(mx, __shfl_xor_sync(0xffffffffu, mx, d));
    float s = __expf(al - mx);
    #pragma unroll
    for (int d = 1; d < 32; d <<= 1)
        s += __shfl_xor_sync(0xffffffffu, s, d);
    #pragma unroll
    for (int d = 1; d < 32; d <<= 1)
        gold += __shfl_xor_sync(0xffffffffu, gold, d);

    if (lane == 0) {
        red[c][h][0] = mx;
        red[c][h][1] = s;
        red[c][h][2] = gold;
    }
    BARC(barid);

    if (h == 0 && lane == 0) {
        float m0 = red[c][0][0], s0 = red[c][0][1];
        float m1 = red[c][1][0], s1 = red[c][1][1];
        float g  = red[c][0][2] + red[c][1][2];
        float M  = fmaxf(m0, m1);
        float S  = s0 * __expf(m0 - M) + s1 * __expf(m1 - M);
        out[b] = (M + __logf(S)) - g;
    }
}

extern "C" void kernel_launch(void* const* d_in, const int* in_sizes, int n_in,
                              void* d_out, int out_size)
{
    const float*        logits = (const float*)d_in[0];
    const unsigned int* tagw   = (const unsigned int*)d_in[1];
    const int*          mask   = (const int*)d_in[2];
    const float*        trans  = (const float*)d_in[3];
    float*              out    = (float*)d_out;

    crf_kernel<<<128, THREADS>>>(logits, tagw, mask, trans, out);
}

// round 9
// speedup vs baseline: 1.0986x; 1.0986x over previous
#include <cuda_runtime.h>

#define L_SEQ 512
#define T_TAGS 64
#define CHAINS 8          // chains per CTA (2 warps each)
#define THREADS 512

#define FMA2(d, a, b) asm("fma.rn.f32x2 %0, %1, %2, %0;" : "+l"(d) : "l"(a), "l"(b))
#define ADD2(d, a)    asm("add.rn.f32x2 %0, %0, %1;"      : "+l"(d) : "l"(a))
#define BARC(id)      asm volatile("bar.sync %0, 64;" :: "r"(id) : "memory")

__device__ __forceinline__ unsigned long long pack2(float x, float y) {
    unsigned long long r;
    asm("mov.b64 %0, {%1, %2};" : "=l"(r) : "f"(x), "f"(y));
    return r;
}

__global__ __launch_bounds__(THREADS, 1)
void crf_kernel(const float* __restrict__ logits,
                const unsigned int* __restrict__ tagw,
                const int* __restrict__ mask,
                const float* __restrict__ trans,
                float* __restrict__ out)
{
    __shared__ float pbuf[2][CHAINS][68];   // p values, double-buffered, +pad
    __shared__ float sbuf[2][CHAINS];       // stale-shift slots, double-buffered
    __shared__ float red[CHAINS][2][4];     // cross-warp scratch

    const int tid  = threadIdx.x;
    const int w    = tid >> 5;
    const int lane = tid & 31;
    const int c    = w >> 1;            // chain within CTA
    const int h    = w & 1;             // warp-half of the chain
    const int j    = (h << 5) + lane;   // this lane owns tag j (0..63)
    const int barid = c;                // no __syncthreads anywhere; 0..7 are free
    const int b    = blockIdx.x * CHAINS + c;

    // ---- tag dtype detection (int64 LE => odd 32-bit words all zero) ----
    unsigned oddacc = 0;
    #pragma unroll
    for (int k = 0; k < 4; ++k) oddacc |= tagw[2 * (lane + 32 * k) + 1];
    const int is64 = __all_sync(0xffffffffu, oddacc == 0) ? 1 : 0;

    // ---- register cache of exp(trans) column j, packed over i-pairs ----
    unsigned long long ec[32];
    #pragma unroll
    for (int i2 = 0; i2 < 32; ++i2) {
        float e0 = __expf(trans[(2 * i2) * 64 + j]);
        float e1 = __expf(trans[(2 * i2 + 1) * 64 + j]);
        ec[i2] = pack2(e0, e1);
    }

    const float* lg = logits + (size_t)b * (L_SEQ * T_TAGS);
    const int mbase = b * L_SEQ;

    // ---- gold score prologue (no sequential dependence): 8 positions/lane ----
    float gp = 0.f;
    int mok = 1;
    #pragma unroll
    for (int k = 0; k < 8; ++k) {
        const int l = j + 64 * k;
        const int mi = mask[mbase + l];
        mok &= (mi == 1);
        const int tg = (int)tagw[is64 ? ((mbase + l) << 1) : (mbase + l)];
        float fm = (float)mi;
        gp += fm * lg[l * T_TAGS + tg];
        if (l > 0) {
            const int tp = (int)tagw[is64 ? ((mbase + l - 1) << 1) : (mbase + l - 1)];
            gp += fm * __ldg(&trans[tp * 64 + tg]);
        }
    }
    mok = __all_sync(0xffffffffu, mok) ? 1 : 0;

    // ---- l = 0 init + cross-warp setup ----
    float al = lg[j];
    if (j == 0) { sbuf[0][c] = al; sbuf[1][c] = al; }
    if (lane == 0) red[c][h][0] = (float)mok;
    BARC(barid);
    const bool allones = (red[c][0][0] != 0.f) && (red[c][1][0] != 0.f);
    float shiftreg = sbuf[1][c];

    float cem = lg[T_TAGS + j];         // emission for step 1

    if (allones) {
        // ======== hot loop: mask-free, gold-free ========
        for (int l = 1; l < L_SEQ; ++l) {
            const int buf = l & 1;
            const int lp = (l + 1 < L_SEQ) ? (l + 1) : (L_SEQ - 1);
            float nem = lg[lp * T_TAGS + j];

            float p = __expf(al - shiftreg);
            pbuf[buf][c][j] = p;
            BARC(barid);
            float nshift = sbuf[(l + 1) & 1][c];

            const ulonglong2* pq = (const ulonglong2*)&pbuf[buf][c][0];
            unsigned long long sA = 0ull, sB = 0ull, sC = 0ull, sD = 0ull;
            #pragma unroll
            for (int k = 0; k < 16; ++k) {
                ulonglong2 pp = pq[k];
                if (k & 1) { FMA2(sC, pp.x, ec[2 * k]); FMA2(sD, pp.y, ec[2 * k + 1]); }
                else       { FMA2(sA, pp.x, ec[2 * k]); FMA2(sB, pp.y, ec[2 * k + 1]); }
            }
            ADD2(sA, sB); ADD2(sC, sD); ADD2(sA, sC);
            float slo, shi;
            asm("mov.b64 {%0, %1}, %2;" : "=f"(slo), "=f"(shi) : "l"(sA));

            al = shiftreg + __logf(slo + shi) + cem;
            if (j == 0) sbuf[buf][c] = al;

            cem = nem; shiftreg = nshift;
        }
    } else {
        // ======== fallback: with mask select ========
        int cm = mask[mbase + 1];
        for (int l = 1; l < L_SEQ; ++l) {
            const int buf = l & 1;
            const int lp = (l + 1 < L_SEQ) ? (l + 1) : (L_SEQ - 1);
            float nem = lg[lp * T_TAGS + j];
            int nm = mask[mbase + lp];

            float p = __expf(al - shiftreg);
            pbuf[buf][c][j] = p;
            BARC(barid);
            float nshift = sbuf[(l + 1) & 1][c];

            const ulonglong2* pq = (const ulonglong2*)&pbuf[buf][c][0];
            unsigned long long sA = 0ull, sB = 0ull, sC = 0ull, sD = 0ull;
            #pragma unroll
            for (int k = 0; k < 16; ++k) {
                ulonglong2 pp = pq[k];
                if (k & 1) { FMA2(sC, pp.x, ec[2 * k]); FMA2(sD, pp.y, ec[2 * k + 1]); }
                else       { FMA2(sA, pp.x, ec[2 * k]); FMA2(sB, pp.y, ec[2 * k + 1]); }
            }
            ADD2(sA, sB); ADD2(sC, sD); ADD2(sA, sC);
            float slo, shi;
            asm("mov.b64 {%0, %1}, %2;" : "=f"(slo), "=f"(shi) : "l"(sA));

            float n = shiftreg + __logf(slo + shi) + cem;
            al = (cm > 0) ? n : al;
            if (j == 0) sbuf[buf][c] = al;

            cem = nem; cm = nm; shiftreg = nshift;
        }
    }

    // ---- epilogue: logsumexp over 64 alphas + gold sum ----
    float mx = al;
    #pragma unroll
    for (int d = 1; d < 32; d <<= 1)
        mx = fmaxf(mx, __shfl_xor_sync(0xffffffffu, mx, d));
    float s = __expf(al - mx);
    #pragma unroll
    for (int d = 1; d < 32; d <<= 1)
        s += __shfl_xor_sync(0xffffffffu, s, d);
    #pragma unroll
    for (int d = 1; d < 32; d <<= 1)
        gp += __shfl_xor_sync(0xffffffffu, gp, d);

    BARC(barid);   // allones flag no longer needed
    if (lane == 0) {
        red[c][h][0] = mx;
        red[c][h][1] = s;
        red[c][h][2] = gp;
    }
    BARC(barid);

    if (h == 0 && lane == 0) {
        float m0 = red[c][0][0], s0 = red[c][0][1];
        float m1 = red[c][1][0], s1 = red[c][1][1];
        float g  = red[c][0][2] + red[c][1][2];
        float M  = fmaxf(m0, m1);
        float S  = s0 * __expf(m0 - M) + s1 * __expf(m1 - M);
        out[b] = (M + __logf(S)) - g;
    }
}

extern "C" void kernel_launch(void* const* d_in, const int* in_sizes, int n_in,
                              void* d_out, int out_size)
{
    const float*        logits = (const float*)d_in[0];
    const unsigned int* tagw   = (const unsigned int*)d_in[1];
    const int*          mask   = (const int*)d_in[2];
    const float*        trans  = (const float*)d_in[3];
    float*              out    = (float*)d_out;

    crf_kernel<<<128, THREADS>>>(logits, tagw, mask, trans, out);
}

// round 10
// speedup vs baseline: 1.3813x; 1.2573x over previous
#include <cuda_runtime.h>

#define L_SEQ 512
#define T_TAGS 64
#define CHAINS 8          // chains per CTA (2 warps each)
#define THREADS 512
#define PFD 4             // emission prefetch depth

#define FMA2(d, a, b) asm("fma.rn.f32x2 %0, %1, %2, %0;" : "+l"(d) : "l"(a), "l"(b))
#define ADD2(d, a)    asm("add.rn.f32x2 %0, %0, %1;"      : "+l"(d) : "l"(a))
#define BARC(id)      asm volatile("bar.sync %0, 64;" :: "r"(id) : "memory")

__device__ __forceinline__ unsigned long long pack2(float x, float y) {
    unsigned long long r;
    asm("mov.b64 %0, {%1, %2};" : "=l"(r) : "f"(x), "f"(y));
    return r;
}

__global__ __launch_bounds__(THREADS, 1)
void crf_kernel(const float* __restrict__ logits,
                const unsigned int* __restrict__ tagw,
                const int* __restrict__ mask,
                const float* __restrict__ trans,
                float* __restrict__ out)
{
    __shared__ float pbuf[2][CHAINS][68];   // p values, double-buffered, +pad
    __shared__ float sbuf[2][CHAINS];       // stale-shift slots, double-buffered
    __shared__ float red[CHAINS][2][4];     // cross-warp scratch

    const int tid  = threadIdx.x;
    const int w    = tid >> 5;
    const int lane = tid & 31;
    const int c    = w >> 1;            // chain within CTA
    const int h    = w & 1;             // warp-half of the chain
    const int j    = (h << 5) + lane;   // this lane owns tag j (0..63)
    const int barid = c;                // no __syncthreads anywhere; 0..7 free
    const int b    = blockIdx.x * CHAINS + c;

    // ---- tag dtype detection (int64 LE => odd 32-bit words all zero) ----
    unsigned oddacc = 0;
    #pragma unroll
    for (int k = 0; k < 4; ++k) oddacc |= tagw[2 * (lane + 32 * k) + 1];
    const int is64 = __all_sync(0xffffffffu, oddacc == 0) ? 1 : 0;

    // ---- register cache of exp(trans) column j, packed over i-pairs ----
    unsigned long long ec[32];
    #pragma unroll
    for (int i2 = 0; i2 < 32; ++i2) {
        float e0 = __expf(trans[(2 * i2) * 64 + j]);
        float e1 = __expf(trans[(2 * i2 + 1) * 64 + j]);
        ec[i2] = pack2(e0, e1);
    }

    const float* lg  = logits + (size_t)b * (L_SEQ * T_TAGS);
    const float* lgj = lg + j;
    const int mbase = b * L_SEQ;

    // ---- gold score prologue (no sequential dependence): 8 positions/lane ----
    float gp = 0.f;
    int mok = 1;
    #pragma unroll
    for (int k = 0; k < 8; ++k) {
        const int l = j + 64 * k;
        const int mi = mask[mbase + l];
        mok &= (mi == 1);
        const int tg = (int)tagw[is64 ? ((mbase + l) << 1) : (mbase + l)];
        float fm = (float)mi;
        gp += fm * lg[l * T_TAGS + tg];
        if (l > 0) {
            const int tp = (int)tagw[is64 ? ((mbase + l - 1) << 1) : (mbase + l - 1)];
            gp += fm * __ldg(&trans[tp * 64 + tg]);
        }
    }
    mok = __all_sync(0xffffffffu, mok) ? 1 : 0;

    // ---- l = 0 init + cross-warp setup ----
    float al = lgj[0];
    if (j == 0) { sbuf[0][c] = al; sbuf[1][c] = al; }
    if (lane == 0) red[c][h][0] = (float)mok;
    BARC(barid);
    const bool allones = (red[c][0][0] != 0.f) && (red[c][1][0] != 0.f);
    float shiftreg = sbuf[1][c];

    // ---- depth-PFD emission prefetch ring: em[k] = emission(step 1+k) ----
    float em[PFD];
    #pragma unroll
    for (int k = 0; k < PFD; ++k) em[k] = __ldg(lgj + (1 + k) * T_TAGS);

    if (allones) {
        // ======== hot loop: mask-free, gold-free, depth-4 LDG pipeline ========
        #pragma unroll 4
        for (int l = 1; l < L_SEQ; ++l) {
            const int slot = (l - 1) & (PFD - 1);
            float cem = em[slot];
            // prefetch emission for step l+PFD (clamped; redundant at tail)
            const int lp = (l + PFD < L_SEQ) ? (l + PFD) : (L_SEQ - 1);
            em[slot] = __ldg(lgj + lp * T_TAGS);

            const int buf = l & 1;
            float p = __expf(al - shiftreg);
            pbuf[buf][c][j] = p;
            BARC(barid);
            float nshift = sbuf[(l + 1) & 1][c];

            const ulonglong2* pq = (const ulonglong2*)&pbuf[buf][c][0];
            unsigned long long sA = 0ull, sB = 0ull, sC = 0ull, sD = 0ull;
            #pragma unroll
            for (int k = 0; k < 16; ++k) {
                ulonglong2 pp = pq[k];
                if (k & 1) { FMA2(sC, pp.x, ec[2 * k]); FMA2(sD, pp.y, ec[2 * k + 1]); }
                else       { FMA2(sA, pp.x, ec[2 * k]); FMA2(sB, pp.y, ec[2 * k + 1]); }
            }
            ADD2(sA, sB); ADD2(sC, sD); ADD2(sA, sC);
            float slo, shi;
            asm("mov.b64 {%0, %1}, %2;" : "=f"(slo), "=f"(shi) : "l"(sA));

            al = shiftreg + __logf(slo + shi) + cem;
            if (j == 0) sbuf[buf][c] = al;

            shiftreg = nshift;
        }
    } else {
        // ======== fallback: with mask select ========
        int cm = mask[mbase + 1];
        #pragma unroll 4
        for (int l = 1; l < L_SEQ; ++l) {
            const int slot = (l - 1) & (PFD - 1);
            float cem = em[slot];
            const int lp = (l + PFD < L_SEQ) ? (l + PFD) : (L_SEQ - 1);
            em[slot] = __ldg(lgj + lp * T_TAGS);
            const int lm1 = (l + 1 < L_SEQ) ? (l + 1) : (L_SEQ - 1);
            int nm = mask[mbase + lm1];

            const int buf = l & 1;
            float p = __expf(al - shiftreg);
            pbuf[buf][c][j] = p;
            BARC(barid);
            float nshift = sbuf[(l + 1) & 1][c];

            const ulonglong2* pq = (const ulonglong2*)&pbuf[buf][c][0];
            unsigned long long sA = 0ull, sB = 0ull, sC = 0ull, sD = 0ull;
            #pragma unroll
            for (int k = 0; k < 16; ++k) {
                ulonglong2 pp = pq[k];
                if (k & 1) { FMA2(sC, pp.x, ec[2 * k]); FMA2(sD, pp.y, ec[2 * k + 1]); }
                else       { FMA2(sA, pp.x, ec[2 * k]); FMA2(sB, pp.y, ec[2 * k + 1]); }
            }
            ADD2(sA, sB); ADD2(sC, sD); ADD2(sA, sC);
            float slo, shi;
            asm("mov.b64 {%0, %1}, %2;" : "=f"(slo), "=f"(shi) : "l"(sA));

            float n = shiftreg + __logf(slo + shi) + cem;
            al = (cm > 0) ? n : al;
            if (j == 0) sbuf[buf][c] = al;

            cm = nm; shiftreg = nshift;
        }
    }

    // ---- epilogue: logsumexp over 64 alphas + gold sum ----
    float mx = al;
    #pragma unroll
    for (int d = 1; d < 32; d <<= 1)
        mx = fmaxf(mx, __shfl_xor_sync(0xffffffffu, mx, d));
    float s = __expf(al - mx);
    #pragma unroll
    for (int d = 1; d < 32; d <<= 1)
        s += __shfl_xor_sync(0xffffffffu, s, d);
    #pragma unroll
    for (int d = 1; d < 32; d <<= 1)
        gp += __shfl_xor_sync(0xffffffffu, gp, d);

    BARC(barid);   // allones flag no longer needed
    if (lane == 0) {
        red[c][h][0] = mx;
        red[c][h][1] = s;
        red[c][h][2] = gp;
    }
    BARC(barid);

    if (h == 0 && lane == 0) {
        float m0 = red[c][0][0], s0 = red[c][0][1];
        float m1 = red[c][1][0], s1 = red[c][1][1];
        float g  = red[c][0][2] + red[c][1][2];
        float M  = fmaxf(m0, m1);
        float S  = s0 * __expf(m0 - M) + s1 * __expf(m1 - M);
        out[b] = (M + __logf(S)) - g;
    }
}

extern "C" void kernel_launch(void* const* d_in, const int* in_sizes, int n_in,
                              void* d_out, int out_size)
{
    const float*        logits = (const float*)d_in[0];
    const unsigned int* tagw   = (const unsigned int*)d_in[1];
    const int*          mask   = (const int*)d_in[2];
    const float*        trans  = (const float*)d_in[3];
    float*              out    = (float*)d_out;

    crf_kernel<<<128, THREADS>>>(logits, tagw, mask, trans, out);
}

// round 13
// speedup vs baseline: 1.5687x; 1.1357x over previous
#include <cuda_runtime.h>

#define L_SEQ 512
#define T_TAGS 64
#define CHAINS 8          // one warp per chain
#define THREADS 256
#define PFD 4             // emission prefetch depth (pre-exponentiated)

#define FMA2(d, a, b) asm("fma.rn.f32x2 %0, %1, %2, %0;" : "+l"(d) : "l"(a), "l"(b))
#define ADD2(d, a)    asm("add.rn.f32x2 %0, %0, %1;"      : "+l"(d) : "l"(a))

__device__ __forceinline__ unsigned long long pack2(float x, float y) {
    unsigned long long r;
    asm("mov.b64 %0, {%1, %2};" : "=l"(r) : "f"(x), "f"(y));
    return r;
}

__global__ __launch_bounds__(THREADS, 1)
void crf_kernel(const float* __restrict__ logits,
                const unsigned int* __restrict__ tagw,
                const int* __restrict__ mask,
                const float* __restrict__ trans,
                float* __restrict__ out)
{
    // u buffers: 64 floats per chain, double-buffered; 68 pad keeps 16B alignment
    __shared__ __align__(16) float ubuf[2][CHAINS][68];

    const int tid  = threadIdx.x;
    const int w    = tid >> 5;          // chain within CTA
    const int lane = tid & 31;
    const int j0   = lane << 1;         // this lane owns tags j0, j0+1
    const int b    = blockIdx.x * CHAINS + w;

    // ---- tag dtype detection (int64 LE => odd 32-bit words all zero) ----
    unsigned oddacc = 0;
    #pragma unroll
    for (int k = 0; k < 4; ++k) oddacc |= tagw[2 * (lane + 32 * k) + 1];
    const int is64 = __all_sync(0xffffffffu, oddacc == 0) ? 1 : 0;

    // ---- register cache of exp(trans): columns j0, j0+1, packed over i-pairs ----
    unsigned long long ec0[32], ec1[32];
    #pragma unroll
    for (int m = 0; m < 32; ++m) {
        float2 ta = *(const float2*)&trans[(2 * m) * 64 + j0];
        float2 tb = *(const float2*)&trans[(2 * m + 1) * 64 + j0];
        ec0[m] = pack2(__expf(ta.x), __expf(tb.x));
        ec1[m] = pack2(__expf(ta.y), __expf(tb.y));
    }

    const float*  lg  = logits + (size_t)b * (L_SEQ * T_TAGS);
    const float2* lg2 = (const float2*)lg;
    const int mbase = b * L_SEQ;

    // ---- gold score prologue (parallel gather): 16 positions per lane ----
    float gp = 0.f;
    int mok = 1;
    #pragma unroll
    for (int k = 0; k < 16; ++k) {
        const int l = lane + 32 * k;
        const int mi = mask[mbase + l];
        mok &= (mi == 1);
        const int tg = (int)tagw[is64 ? ((mbase + l) << 1) : (mbase + l)];
        float fm = (float)mi;
        gp += fm * lg[l * T_TAGS + tg];
        if (l > 0) {
            const int tp = (int)tagw[is64 ? ((mbase + l - 1) << 1) : (mbase + l - 1)];
            gp += fm * __ldg(&trans[tp * 64 + tg]);
        }
    }
    mok = __all_sync(0xffffffffu, mok) ? 1 : 0;

    // ---- init: u = exp(alpha0 - alpha0[0]); LR carries the log offset ----
    const float a00 = __ldg(lg);              // alpha0[0], broadcast load
    float2 alv = lg2[lane];                   // alpha0 at j0, j0+1
    float mu0 = __expf(alv.x - a00);
    float mu1 = __expf(alv.y - a00);
    *(float2*)&ubuf[1][w][j0] = make_float2(mu0, mu1);   // step 1 reads buf 1
    double lr = (double)a00;

    // ---- emission ring, PRE-EXPONENTIATED: eem[k] = exp(em(step 1+k)) ----
    float2 eem[PFD];
    #pragma unroll
    for (int k = 0; k < PFD; ++k) {
        float2 e = __ldg(&lg2[(1 + k) * 32 + lane]);
        eem[k] = make_float2(__expf(e.x), __expf(e.y));
    }
    __syncwarp();

    if (mok) {
        // ======== hot loop: linear space, no log/exp on the chain ========
        #pragma unroll 4
        for (int l = 1; l < L_SEQ; ++l) {
            const int slot = (l - 1) & (PFD - 1);
            float2 f = eem[slot];
            const int lp = (l + PFD < L_SEQ) ? (l + PFD) : (L_SEQ - 1);
            float2 raw = __ldg(&lg2[lp * 32 + lane]);    // prefetch emission

            // matvec: s[j] = sum_i u[i] * E[i][j]
            const ulonglong2* pq = (const ulonglong2*)&ubuf[l & 1][w][0];
            unsigned long long A0 = 0, B0 = 0, C0 = 0, D0 = 0;
            unsigned long long A1 = 0, B1 = 0, C1 = 0, D1 = 0;
            float u0first;
            #pragma unroll
            for (int k = 0; k < 16; ++k) {
                ulonglong2 pp = pq[k];
                if (k == 0) {
                    float dummy;
                    asm("mov.b64 {%0, %1}, %2;" : "=f"(u0first), "=f"(dummy) : "l"(pp.x));
                }
                if (k & 1) {
                    FMA2(C0, pp.x, ec0[2 * k]); FMA2(D0, pp.y, ec0[2 * k + 1]);
                    FMA2(C1, pp.x, ec1[2 * k]); FMA2(D1, pp.y, ec1[2 * k + 1]);
                } else {
                    FMA2(A0, pp.x, ec0[2 * k]); FMA2(B0, pp.y, ec0[2 * k + 1]);
                    FMA2(A1, pp.x, ec1[2 * k]); FMA2(B1, pp.y, ec1[2 * k + 1]);
                }
            }
            // off-path: refill ring, normalizer, log-carry
            eem[slot] = make_float2(__expf(raw.x), __expf(raw.y));
            float r;
            asm("rcp.approx.ftz.f32 %0, %1;" : "=f"(r) : "f"(u0first));
            lr += (double)__logf(u0first);

            ADD2(A0, B0); ADD2(C0, D0); ADD2(A0, C0);
            ADD2(A1, B1); ADD2(C1, D1); ADD2(A1, C1);
            float s0lo, s0hi, s1lo, s1hi;
            asm("mov.b64 {%0, %1}, %2;" : "=f"(s0lo), "=f"(s0hi) : "l"(A0));
            asm("mov.b64 {%0, %1}, %2;" : "=f"(s1lo), "=f"(s1hi) : "l"(A1));

            mu0 = (s0lo + s0hi) * (f.x * r);
            mu1 = (s1lo + s1hi) * (f.y * r);
            *(float2*)&ubuf[(l + 1) & 1][w][j0] = make_float2(mu0, mu1);
            __syncwarp();
        }
    } else {
        // ======== fallback: with mask select (uniform-scaling exact) ========
        for (int l = 1; l < L_SEQ; ++l) {
            const int slot = (l - 1) & (PFD - 1);
            float2 f = eem[slot];
            const int lp = (l + PFD < L_SEQ) ? (l + PFD) : (L_SEQ - 1);
            float2 raw = __ldg(&lg2[lp * 32 + lane]);
            const int cm = mask[mbase + l];

            const ulonglong2* pq = (const ulonglong2*)&ubuf[l & 1][w][0];
            unsigned long long A0 = 0, B0 = 0, C0 = 0, D0 = 0;
            unsigned long long A1 = 0, B1 = 0, C1 = 0, D1 = 0;
            float u0first;
            #pragma unroll
            for (int k = 0; k < 16; ++k) {
                ulonglong2 pp = pq[k];
                if (k == 0) {
                    float dummy;
                    asm("mov.b64 {%0, %1}, %2;" : "=f"(u0first), "=f"(dummy) : "l"(pp.x));
                }
                if (k & 1) {
                    FMA2(C0, pp.x, ec0[2 * k]); FMA2(D0, pp.y, ec0[2 * k + 1]);
                    FMA2(C1, pp.x, ec1[2 * k]); FMA2(D1, pp.y, ec1[2 * k + 1]);
                } else {
                    FMA2(A0, pp.x, ec0[2 * k]); FMA2(B0, pp.y, ec0[2 * k + 1]);
                    FMA2(A1, pp.x, ec1[2 * k]); FMA2(B1, pp.y, ec1[2 * k + 1]);
                }
            }
            eem[slot] = make_float2(__expf(raw.x), __expf(raw.y));
            float r;
            asm("rcp.approx.ftz.f32 %0, %1;" : "=f"(r) : "f"(u0first));
            lr += (double)__logf(u0first);

            ADD2(A0, B0); ADD2(C0, D0); ADD2(A0, C0);
            ADD2(A1, B1); ADD2(C1, D1); ADD2(A1, C1);
            float s0lo, s0hi, s1lo, s1hi;
            asm("mov.b64 {%0, %1}, %2;" : "=f"(s0lo), "=f"(s0hi) : "l"(A0));
            asm("mov.b64 {%0, %1}, %2;" : "=f"(s1lo), "=f"(s1hi) : "l"(A1));

            float n0 = (s0lo + s0hi) * (f.x * r);
            float n1 = (s1lo + s1hi) * (f.y * r);
            // masked step: alpha unchanged => u scaled by the uniform r only
            mu0 = (cm > 0) ? n0 : mu0 * r;
            mu1 = (cm > 0) ? n1 : mu1 * r;
            *(float2*)&ubuf[(l + 1) & 1][w][j0] = make_float2(mu0, mu1);
            __syncwarp();
        }
    }

    // ---- epilogue: logZ = LR + log(sum u); subtract gold ----
    float su = mu0 + mu1;
    #pragma unroll
    for (int d = 1; d < 32; d <<= 1)
        su += __shfl_xor_sync(0xffffffffu, su, d);
    #pragma unroll
    for (int d = 1; d < 32; d <<= 1)
        gp += __shfl_xor_sync(0xffffffffu, gp, d);

    if (lane == 0)
        out[b] = (float)(lr + (double)__logf(su)) - gp;
}

extern "C" void kernel_launch(void* const* d_in, const int* in_sizes, int n_in,
                              void* d_out, int out_size)
{
    const float*        logits = (const float*)d_in[0];
    const unsigned int* tagw   = (const unsigned int*)d_in[1];
    const int*          mask   = (const int*)d_in[2];
    const float*        trans  = (const float*)d_in[3];
    float*              out    = (float*)d_out;

    crf_kernel<<<128, THREADS>>>(logits, tagw, mask, trans, out);
}